// round 3
// baseline (speedup 1.0000x reference)
#include <cuda_runtime.h>
#include <cstddef>

// Problem constants
#define BATCH 4
#define SEQ   2048
#define EMB   512
#define HEADS 8
#define KDIM  64
#define TOKENS (BATCH * SEQ)          // 8192

// Scratch (allocation-free rule: __device__ globals)
__device__ float g_q  [TOKENS * EMB];   // Q = x @ Wq, [tok, h*64+d]
__device__ float g_ctx[TOKENS * EMB];   // context,    [tok, h*64+d]

// ---------------------------------------------------------------------------
// helpers
// ---------------------------------------------------------------------------
__device__ __forceinline__ float tf32r(float x) {
    float y;
    asm("cvt.rna.tf32.f32 %0, %1;" : "=f"(y) : "f"(x));
    return y;
}

__device__ __forceinline__ void mma_tf32(float* c,
                                         float a0, float a1, float a2, float a3,
                                         float b0, float b1)
{
    asm volatile(
        "mma.sync.aligned.m16n8k8.row.col.f32.tf32.tf32.f32 "
        "{%0,%1,%2,%3}, {%4,%5,%6,%7}, {%8,%9}, {%0,%1,%2,%3};\n"
        : "+f"(c[0]), "+f"(c[1]), "+f"(c[2]), "+f"(c[3])
        : "r"(__float_as_uint(a0)), "r"(__float_as_uint(a1)),
          "r"(__float_as_uint(a2)), "r"(__float_as_uint(a3)),
          "r"(__float_as_uint(b0)), "r"(__float_as_uint(b1)));
}

// Pads (float2 units). Chosen so fragment loads are conflict-free per
// 16-lane phase: K-pattern bank=8g+2t, V/B-pattern bank=8t+2g, A bank=8row+2t.
#define KVP 68
#define AP  36
#define BP  68

#define ATTN_SMEM (2 * 64 * KVP * (int)sizeof(float2))          // 69632 B
#define GEMM_SMEM ((128 * AP + 32 * BP) * (int)sizeof(float2))  // 54272 B

// ---------------------------------------------------------------------------
// Split-tf32 GEMM: C[M,N] = A[M,K] @ B[K,N], ~fp32 accuracy (3-term split).
// CTA = 256 thr = 8 warps, 128x64 output tile (warp: 16x64), BK=32.
// mma.sync.m16n8k8 fragment layout (row.col), g=lane>>2, t=lane&3:
//   A: a0=(g,t) a1=(g+8,t) a2=(g,t+4) a3=(g+8,t+4)
//   B: b0=(k=t,n=g) b1=(k=t+4,n=g)
//   C: c0=(g,2t) c1=(g,2t+1) c2=(g+8,2t) c3=(g+8,2t+1)
// ---------------------------------------------------------------------------
__global__ __launch_bounds__(256) void gemm_tf32(
    const float* __restrict__ A, const float* __restrict__ Bm,
    float* __restrict__ C, int M, int N, int K)
{
    extern __shared__ float2 dsm[];
    float2* A2 = dsm;                 // [128][AP]  {hi,lo}
    float2* B2 = dsm + 128 * AP;      // [32][BP]   {hi,lo}

    const int tid  = threadIdx.x;
    const int warp = tid >> 5, lane = tid & 31;
    const int g = lane >> 2, t = lane & 3;
    const int bn = blockIdx.x << 6;
    const int bm = blockIdx.y << 7;
    const int wm = warp << 4;         // warp's row offset in tile

    float acc[8][4];
#pragma unroll
    for (int n = 0; n < 8; ++n)
#pragma unroll
        for (int i = 0; i < 4; ++i) acc[n][i] = 0.f;

    for (int kt = 0; kt < K; kt += 32) {
        __syncthreads();
        {   // A tile: 128 rows x 32 cols; thread = half row
            const int r  = tid >> 1;
            const int cb = (tid & 1) << 4;
#pragma unroll
            for (int i = 0; i < 4; ++i) {
                const int c = cb + (i << 2);
                float4 a = *(const float4*)&A[(size_t)(bm + r) * K + kt + c];
                float h0 = tf32r(a.x), h1 = tf32r(a.y);
                float h2 = tf32r(a.z), h3 = tf32r(a.w);
                *(float4*)&A2[r * AP + c]     = make_float4(h0, a.x - h0, h1, a.y - h1);
                *(float4*)&A2[r * AP + c + 2] = make_float4(h2, a.z - h2, h3, a.w - h3);
            }
            // B tile: 32 rows x 64 cols; thread = 8 cols of one row
            const int rb = tid >> 3;
            const int cb2 = (tid & 7) << 3;
#pragma unroll
            for (int i = 0; i < 2; ++i) {
                const int c = cb2 + (i << 2);
                float4 b = *(const float4*)&Bm[(size_t)(kt + rb) * N + bn + c];
                float h0 = tf32r(b.x), h1 = tf32r(b.y);
                float h2 = tf32r(b.z), h3 = tf32r(b.w);
                *(float4*)&B2[rb * BP + c]     = make_float4(h0, b.x - h0, h1, b.y - h1);
                *(float4*)&B2[rb * BP + c + 2] = make_float4(h2, b.z - h2, h3, b.w - h3);
            }
        }
        __syncthreads();

#pragma unroll
        for (int kc = 0; kc < 4; ++kc) {
            float2 a0 = A2[(wm + g)     * AP + kc * 8 + t];
            float2 a1 = A2[(wm + g + 8) * AP + kc * 8 + t];
            float2 a2 = A2[(wm + g)     * AP + kc * 8 + t + 4];
            float2 a3 = A2[(wm + g + 8) * AP + kc * 8 + t + 4];
#pragma unroll
            for (int n = 0; n < 8; ++n) {
                float2 b0 = B2[(kc * 8 + t)     * BP + n * 8 + g];
                float2 b1 = B2[(kc * 8 + t + 4) * BP + n * 8 + g];
                mma_tf32(acc[n], a0.x, a1.x, a2.x, a3.x, b0.x, b1.x);
                mma_tf32(acc[n], a0.x, a1.x, a2.x, a3.x, b0.y, b1.y);
                mma_tf32(acc[n], a0.y, a1.y, a2.y, a3.y, b0.x, b1.x);
            }
        }
    }

    const int row0 = bm + wm + g, row1 = row0 + 8;
#pragma unroll
    for (int n = 0; n < 8; ++n) {
        *(float2*)&C[(size_t)row0 * N + bn + n * 8 + 2 * t] = make_float2(acc[n][0], acc[n][1]);
        *(float2*)&C[(size_t)row1 * N + bn + n * 8 + 2 * t] = make_float2(acc[n][2], acc[n][3]);
    }
}

// ---------------------------------------------------------------------------
// Flash attention on tensor cores, tf32 3-way split, K/V pre-split in smem.
// 1 CTA = 256 thr = 8 warps per (b, h, 128-query tile); warp owns 16 q rows.
// ---------------------------------------------------------------------------
__global__ __launch_bounds__(256) void attn_mma(
    const float* __restrict__ Q,   // [tok, 512] from g_q
    const float* __restrict__ Kg,  // [B,H,S,64]
    const float* __restrict__ Vg,  // [B,H,S,64]
    float* __restrict__ Ctx)       // [tok, 512]
{
    extern __shared__ float2 dsm[];
    float2* Ks2 = dsm;             // [64][KVP] {hi,lo} of K[r][d]
    float2* Vs2 = dsm + 64 * KVP;  // [64][KVP] {hi,lo} of V[r][d]

    const int tid  = threadIdx.x;
    const int warp = tid >> 5, lane = tid & 31;
    const int gq = lane >> 2, tq = lane & 3;
    const int bh = blockIdx.y;
    const int b  = bh >> 3, h = bh & 7;
    const int q0 = blockIdx.x << 7;
    const int row0 = q0 + warp * 16 + gq;
    const int row1 = row0 + 8;

    // ---- Q fragments (hi/lo split), pre-scaled by 1/sqrt(64) ----
    float qh[8][4], ql[8][4];
    {
        const float* qp = Q + (size_t)(b * SEQ) * EMB + h * KDIM;
#pragma unroll
        for (int c = 0; c < 8; ++c) {
            float v[4];
            v[0] = qp[(size_t)row0 * EMB + c * 8 + tq]     * 0.125f;
            v[1] = qp[(size_t)row1 * EMB + c * 8 + tq]     * 0.125f;
            v[2] = qp[(size_t)row0 * EMB + c * 8 + tq + 4] * 0.125f;
            v[3] = qp[(size_t)row1 * EMB + c * 8 + tq + 4] * 0.125f;
#pragma unroll
            for (int i = 0; i < 4; ++i) {
                qh[c][i] = tf32r(v[i]);
                ql[c][i] = v[i] - qh[c][i];
            }
        }
    }

    float oacc[8][4];
#pragma unroll
    for (int n = 0; n < 8; ++n)
#pragma unroll
        for (int i = 0; i < 4; ++i) oacc[n][i] = 0.f;
    float m0 = -1e30f, m1 = -1e30f, l0 = 0.f, l1 = 0.f;

    const float* kb = Kg + (size_t)bh * SEQ * KDIM;
    const float* vb = Vg + (size_t)bh * SEQ * KDIM;

    for (int kt = 0; kt < SEQ / 64; ++kt) {
        __syncthreads();
#pragma unroll
        for (int it = 0; it < 4; ++it) {
            int idx = tid + (it << 8);
            int r = idx >> 4, c4 = (idx & 15) << 2;
            float4 kv = *(const float4*)&kb[((size_t)(kt << 6) + r) * KDIM + c4];
            float4 vv = *(const float4*)&vb[((size_t)(kt << 6) + r) * KDIM + c4];
            float kh0 = tf32r(kv.x), kh1 = tf32r(kv.y), kh2 = tf32r(kv.z), kh3 = tf32r(kv.w);
            *(float4*)&Ks2[r * KVP + c4]     = make_float4(kh0, kv.x - kh0, kh1, kv.y - kh1);
            *(float4*)&Ks2[r * KVP + c4 + 2] = make_float4(kh2, kv.z - kh2, kh3, kv.w - kh3);
            float vh0 = tf32r(vv.x), vh1 = tf32r(vv.y), vh2 = tf32r(vv.z), vh3 = tf32r(vv.w);
            *(float4*)&Vs2[r * KVP + c4]     = make_float4(vh0, vv.x - vh0, vh1, vv.y - vh1);
            *(float4*)&Vs2[r * KVP + c4 + 2] = make_float4(vh2, vv.z - vh2, vh3, vv.w - vh3);
        }
        __syncthreads();

        // ---- S = Q K^T (16x64 per warp), tf32 3x split ----
        float sacc[8][4];
#pragma unroll
        for (int n = 0; n < 8; ++n)
#pragma unroll
            for (int i = 0; i < 4; ++i) sacc[n][i] = 0.f;

#pragma unroll
        for (int kc = 0; kc < 8; ++kc) {
#pragma unroll
            for (int n = 0; n < 8; ++n) {
                float2 b0 = Ks2[(n * 8 + gq) * KVP + kc * 8 + tq];
                float2 b1 = Ks2[(n * 8 + gq) * KVP + kc * 8 + tq + 4];
                mma_tf32(sacc[n], qh[kc][0], qh[kc][1], qh[kc][2], qh[kc][3], b0.x, b1.x);
                mma_tf32(sacc[n], qh[kc][0], qh[kc][1], qh[kc][2], qh[kc][3], b0.y, b1.y);
                mma_tf32(sacc[n], ql[kc][0], ql[kc][1], ql[kc][2], ql[kc][3], b0.x, b1.x);
            }
        }

        // ---- online softmax (row0 via c0/c1, row1 via c2/c3; quad-reduce) ----
        float tm0 = -1e30f, tm1 = -1e30f;
#pragma unroll
        for (int n = 0; n < 8; ++n) {
            tm0 = fmaxf(tm0, fmaxf(sacc[n][0], sacc[n][1]));
            tm1 = fmaxf(tm1, fmaxf(sacc[n][2], sacc[n][3]));
        }
        tm0 = fmaxf(tm0, __shfl_xor_sync(0xffffffffu, tm0, 1));
        tm0 = fmaxf(tm0, __shfl_xor_sync(0xffffffffu, tm0, 2));
        tm1 = fmaxf(tm1, __shfl_xor_sync(0xffffffffu, tm1, 1));
        tm1 = fmaxf(tm1, __shfl_xor_sync(0xffffffffu, tm1, 2));
        float n0 = fmaxf(m0, tm0), n1 = fmaxf(m1, tm1);
        float sc0 = __expf(m0 - n0), sc1 = __expf(m1 - n1);
        m0 = n0; m1 = n1;
        float ps0 = 0.f, ps1 = 0.f;
#pragma unroll
        for (int n = 0; n < 8; ++n) {
            sacc[n][0] = __expf(sacc[n][0] - n0); ps0 += sacc[n][0];
            sacc[n][1] = __expf(sacc[n][1] - n0); ps0 += sacc[n][1];
            sacc[n][2] = __expf(sacc[n][2] - n1); ps1 += sacc[n][2];
            sacc[n][3] = __expf(sacc[n][3] - n1); ps1 += sacc[n][3];
        }
        ps0 += __shfl_xor_sync(0xffffffffu, ps0, 1);
        ps0 += __shfl_xor_sync(0xffffffffu, ps0, 2);
        ps1 += __shfl_xor_sync(0xffffffffu, ps1, 1);
        ps1 += __shfl_xor_sync(0xffffffffu, ps1, 2);
        l0 = l0 * sc0 + ps0;
        l1 = l1 * sc1 + ps1;
#pragma unroll
        for (int n = 0; n < 8; ++n) {
            oacc[n][0] *= sc0; oacc[n][1] *= sc0;
            oacc[n][2] *= sc1; oacc[n][3] *= sc1;
        }

        // ---- O += P V : P accumulator frags -> A frags via shuffles ----
        const int srcA = (lane & ~3) | (tq >> 1);   // cols q   (q = tq)
        const int srcB = srcA + 2;                  // cols q+4
#pragma unroll
        for (int kc = 0; kc < 8; ++kc) {
            float v0 = __shfl_sync(0xffffffffu, sacc[kc][0], srcA);
            float v1 = __shfl_sync(0xffffffffu, sacc[kc][1], srcA);
            float v2 = __shfl_sync(0xffffffffu, sacc[kc][2], srcA);
            float v3 = __shfl_sync(0xffffffffu, sacc[kc][3], srcA);
            float w0 = __shfl_sync(0xffffffffu, sacc[kc][0], srcB);
            float w1 = __shfl_sync(0xffffffffu, sacc[kc][1], srcB);
            float w2 = __shfl_sync(0xffffffffu, sacc[kc][2], srcB);
            float w3 = __shfl_sync(0xffffffffu, sacc[kc][3], srcB);
            const bool odd = (tq & 1);
            float a0 = odd ? v1 : v0;   // P[row0][q]
            float a1 = odd ? v3 : v2;   // P[row1][q]
            float a2 = odd ? w1 : w0;   // P[row0][q+4]
            float a3 = odd ? w3 : w2;   // P[row1][q+4]
            float ah0 = tf32r(a0), al0 = a0 - ah0;
            float ah1 = tf32r(a1), al1 = a1 - ah1;
            float ah2 = tf32r(a2), al2 = a2 - ah2;
            float ah3 = tf32r(a3), al3 = a3 - ah3;
#pragma unroll
            for (int dt = 0; dt < 8; ++dt) {
                float2 b0 = Vs2[(kc * 8 + tq)     * KVP + dt * 8 + gq];
                float2 b1 = Vs2[(kc * 8 + tq + 4) * KVP + dt * 8 + gq];
                mma_tf32(oacc[dt], ah0, ah1, ah2, ah3, b0.x, b1.x);
                mma_tf32(oacc[dt], al0, al1, al2, al3, b0.x, b1.x);
                mma_tf32(oacc[dt], ah0, ah1, ah2, ah3, b0.y, b1.y);
            }
        }
    }

    // ---- normalize + write ctx [tok, h*64+d] ----
    float inv0 = 1.f / l0, inv1 = 1.f / l1;
    float* cp = Ctx + (size_t)(b * SEQ) * EMB + h * KDIM;
#pragma unroll
    for (int dt = 0; dt < 8; ++dt) {
        *(float2*)&cp[(size_t)row0 * EMB + dt * 8 + 2 * tq] =
            make_float2(oacc[dt][0] * inv0, oacc[dt][1] * inv0);
        *(float2*)&cp[(size_t)row1 * EMB + dt * 8 + 2 * tq] =
            make_float2(oacc[dt][2] * inv1, oacc[dt][3] * inv1);
    }
}

// ---------------------------------------------------------------------------
extern "C" void kernel_launch(void* const* d_in, const int* in_sizes, int n_in,
                              void* d_out, int out_size)
{
    const float* x   = (const float*)d_in[0];   // [4,2048,512]
    const float* key = (const float*)d_in[1];   // [4,8,2048,64]
    const float* val = (const float*)d_in[2];   // [4,8,2048,64]
    const float* wq  = (const float*)d_in[3];   // [512,512]
    const float* wo  = (const float*)d_in[4];   // [512,512]
    float* out = (float*)d_out;                 // [4,2048,512]

    float *qptr, *cptr;
    cudaGetSymbolAddress((void**)&qptr, g_q);
    cudaGetSymbolAddress((void**)&cptr, g_ctx);

    cudaFuncSetAttribute(gemm_tf32, cudaFuncAttributeMaxDynamicSharedMemorySize, GEMM_SMEM);
    cudaFuncSetAttribute(attn_mma,  cudaFuncAttributeMaxDynamicSharedMemorySize, ATTN_SMEM);

    // 1) Q = x @ Wq   : [8192,512] x [512,512]
    gemm_tf32<<<dim3(EMB / 64, TOKENS / 128), 256, GEMM_SMEM>>>(x, wq, qptr, TOKENS, EMB, EMB);
    // 2) attention    : grid (q-tiles of 128, b*h)
    attn_mma<<<dim3(SEQ / 128, BATCH * HEADS), 256, ATTN_SMEM>>>(qptr, key, val, cptr);
    // 3) out = ctx @ Wo
    gemm_tf32<<<dim3(EMB / 64, TOKENS / 128), 256, GEMM_SMEM>>>(cptr, wo, out, TOKENS, EMB, EMB);
}

// round 4
// speedup vs baseline: 1.8276x; 1.8276x over previous
#include <cuda_runtime.h>
#include <cstdint>
#include <cstddef>

// Problem constants
#define BATCH 4
#define SEQ   2048
#define EMB   512
#define HEADS 8
#define KDIM  64
#define TOKENS (BATCH * SEQ)          // 8192

// Scratch (allocation-free rule: __device__ globals)
__device__ float g_q  [TOKENS * EMB];   // Q = x @ Wq, [tok, h*64+d]
__device__ float g_ctx[TOKENS * EMB];   // context,    [tok, h*64+d]

// ---------------------------------------------------------------------------
// helpers: bf16 hi/lo split (a ~= ah + al, accurate to ~2^-17)
// ---------------------------------------------------------------------------
__device__ __forceinline__ uint32_t pack2(float lo, float hi) {
    uint32_t r;
    asm("cvt.rn.bf16x2.f32 %0, %1, %2;" : "=r"(r) : "f"(hi), "f"(lo));
    return r;
}
__device__ __forceinline__ float unlo(uint32_t p) { return __uint_as_float(p << 16); }
__device__ __forceinline__ float unhi(uint32_t p) { return __uint_as_float(p & 0xffff0000u); }
__device__ __forceinline__ uint32_t resid2(float lo, float hi, uint32_t h) {
    return pack2(lo - unlo(h), hi - unhi(h));
}

// mma.sync m16n8k16 bf16 (f32 accum). Fragment layout (g=lane>>2, t=lane&3):
//   A: a0={(g,2t),(g,2t+1)} a1={(g+8,2t),(g+8,2t+1)} a2={(g,2t+8),(g,2t+9)} a3={(g+8,2t+8),(g+8,2t+9)}
//   B: b0={(k=2t,n=g),(2t+1,g)}  b1={(2t+8,g),(2t+9,g)}
//   C: c0=(g,2t) c1=(g,2t+1) c2=(g+8,2t) c3=(g+8,2t+1)
__device__ __forceinline__ void mma_bf16(float* c,
                                         uint32_t a0, uint32_t a1, uint32_t a2, uint32_t a3,
                                         uint32_t b0, uint32_t b1)
{
    asm volatile(
        "mma.sync.aligned.m16n8k16.row.col.f32.bf16.bf16.f32 "
        "{%0,%1,%2,%3}, {%4,%5,%6,%7}, {%8,%9}, {%0,%1,%2,%3};\n"
        : "+f"(c[0]), "+f"(c[1]), "+f"(c[2]), "+f"(c[3])
        : "r"(a0), "r"(a1), "r"(a2), "r"(a3), "r"(b0), "r"(b1));
}

// smem row widths (uint32 words), chosen for conflict-free fragment LDS:
//   K-style  [row][dpair]:   W=36 -> bank 4g+t      (distinct over warp)
//   V-style  [rpair][col]:   W=72 -> bank 8t+g      (distinct over warp)
//   A-style  [row][kpair]:   W=20 -> bank 4*(5g%8)+t (distinct over warp)
#define KW 36
#define VW 72
#define AW 20

// ---------------------------------------------------------------------------
// Split-bf16 GEMM: C[M,N] = A[M,K] @ B[K,N], ~2^-17 accuracy per operand.
// CTA = 256 thr = 8 warps, 128x64 tile (warp: 16x64), BK=32 (2 k16 chunks).
// ---------------------------------------------------------------------------
__global__ __launch_bounds__(256) void gemm_bf16s(
    const float* __restrict__ A, const float* __restrict__ Bm,
    float* __restrict__ C, int M, int N, int K)
{
    __shared__ uint32_t Ahi[128 * AW], Alo[128 * AW];
    __shared__ uint32_t Bhi[16 * VW],  Blo[16 * VW];

    const int tid  = threadIdx.x;
    const int warp = tid >> 5, lane = tid & 31;
    const int g = lane >> 2, t = lane & 3;
    const int bn = blockIdx.x << 6;
    const int bm = blockIdx.y << 7;
    const int wm = warp << 4;

    float acc[8][4];
#pragma unroll
    for (int n = 0; n < 8; ++n)
#pragma unroll
        for (int i = 0; i < 4; ++i) acc[n][i] = 0.f;

    for (int kt = 0; kt < K; kt += 32) {
        __syncthreads();
        {   // A tile 128x32: thread = half row (16 cols)
            const int r   = tid >> 1;
            const int c16 = (tid & 1) << 4;
            const float* ar = &A[(size_t)(bm + r) * K + kt + c16];
#pragma unroll
            for (int i = 0; i < 4; ++i) {
                float4 a = *(const float4*)&ar[4 * i];
                uint32_t h0 = pack2(a.x, a.y), h1 = pack2(a.z, a.w);
                int w = r * AW + (c16 >> 1) + 2 * i;
                *(uint2*)&Ahi[w] = make_uint2(h0, h1);
                *(uint2*)&Alo[w] = make_uint2(resid2(a.x, a.y, h0), resid2(a.z, a.w, h1));
            }
            // B tile 32x64 -> row-pair layout Bhi[rp][n]
            const int n2 = (lane) * 2 - (tid & 32) * 0;   // see below
            const int nn = (tid & 31) << 1;
            const int kk = (tid >> 5) << 2;
            (void)n2;
#pragma unroll
            for (int i = 0; i < 2; ++i) {
                int r0 = kk + 2 * i;
                float2 p = *(const float2*)&Bm[(size_t)(kt + r0)     * N + bn + nn];
                float2 q = *(const float2*)&Bm[(size_t)(kt + r0 + 1) * N + bn + nn];
                uint32_t h0 = pack2(p.x, q.x), h1 = pack2(p.y, q.y);
                int w = (r0 >> 1) * VW + nn;
                *(uint2*)&Bhi[w] = make_uint2(h0, h1);
                *(uint2*)&Blo[w] = make_uint2(resid2(p.x, q.x, h0), resid2(p.y, q.y, h1));
            }
        }
        __syncthreads();

#pragma unroll
        for (int kc = 0; kc < 2; ++kc) {
            const int wa = (wm + g) * AW + kc * 8 + t;
            uint32_t ah0 = Ahi[wa],            ah1 = Ahi[wa + 8 * AW];
            uint32_t ah2 = Ahi[wa + 4],        ah3 = Ahi[wa + 8 * AW + 4];
            uint32_t al0 = Alo[wa],            al1 = Alo[wa + 8 * AW];
            uint32_t al2 = Alo[wa + 4],        al3 = Alo[wa + 8 * AW + 4];
#pragma unroll
            for (int n = 0; n < 8; ++n) {
                const int wb = (kc * 8 + t) * VW + n * 8 + g;
                uint32_t bh0 = Bhi[wb], bh1 = Bhi[wb + 4 * VW];
                uint32_t bl0 = Blo[wb], bl1 = Blo[wb + 4 * VW];
                mma_bf16(acc[n], ah0, ah1, ah2, ah3, bh0, bh1);
                mma_bf16(acc[n], al0, al1, al2, al3, bh0, bh1);
                mma_bf16(acc[n], ah0, ah1, ah2, ah3, bl0, bl1);
            }
        }
    }

    const int row0 = bm + wm + g, row1 = row0 + 8;
#pragma unroll
    for (int n = 0; n < 8; ++n) {
        *(float2*)&C[(size_t)row0 * N + bn + n * 8 + 2 * t] = make_float2(acc[n][0], acc[n][1]);
        *(float2*)&C[(size_t)row1 * N + bn + n * 8 + 2 * t] = make_float2(acc[n][2], acc[n][3]);
    }
}

// ---------------------------------------------------------------------------
// Flash attention, split-bf16 m16n8k16. 1 CTA = 8 warps per (b,h,128-q tile).
// P->A fragment conversion is pure packing (accumulator pairs == A pairs).
// ---------------------------------------------------------------------------
__global__ __launch_bounds__(256) void attn_mma(
    const float* __restrict__ Q,   // [tok, 512] from g_q
    const float* __restrict__ Kg,  // [B,H,S,64]
    const float* __restrict__ Vg,  // [B,H,S,64]
    float* __restrict__ Ctx)       // [tok, 512]
{
    __shared__ uint32_t Khi[64 * KW], Klo[64 * KW];   // [key][dpair]
    __shared__ uint32_t Vhi[32 * VW], Vlo[32 * VW];   // [rowpair][d]

    const int tid  = threadIdx.x;
    const int warp = tid >> 5, lane = tid & 31;
    const int gq = lane >> 2, tq = lane & 3;
    const int bh = blockIdx.y;
    const int b  = bh >> 3, h = bh & 7;
    const int q0 = blockIdx.x << 7;
    const int row0 = q0 + warp * 16 + gq;
    const int row1 = row0 + 8;

    // ---- Q fragments (bf16 hi/lo), pre-scaled by 1/sqrt(64) ----
    uint32_t qh[4][4], ql[4][4];
    {
        const float* qp = Q + (size_t)(b * SEQ) * EMB + h * KDIM;
#pragma unroll
        for (int kc = 0; kc < 4; ++kc) {
            float2 v0 = *(const float2*)&qp[(size_t)row0 * EMB + kc * 16 + 2 * tq];
            float2 v1 = *(const float2*)&qp[(size_t)row1 * EMB + kc * 16 + 2 * tq];
            float2 v2 = *(const float2*)&qp[(size_t)row0 * EMB + kc * 16 + 2 * tq + 8];
            float2 v3 = *(const float2*)&qp[(size_t)row1 * EMB + kc * 16 + 2 * tq + 8];
            v0.x *= 0.125f; v0.y *= 0.125f; v1.x *= 0.125f; v1.y *= 0.125f;
            v2.x *= 0.125f; v2.y *= 0.125f; v3.x *= 0.125f; v3.y *= 0.125f;
            qh[kc][0] = pack2(v0.x, v0.y); ql[kc][0] = resid2(v0.x, v0.y, qh[kc][0]);
            qh[kc][1] = pack2(v1.x, v1.y); ql[kc][1] = resid2(v1.x, v1.y, qh[kc][1]);
            qh[kc][2] = pack2(v2.x, v2.y); ql[kc][2] = resid2(v2.x, v2.y, qh[kc][2]);
            qh[kc][3] = pack2(v3.x, v3.y); ql[kc][3] = resid2(v3.x, v3.y, qh[kc][3]);
        }
    }

    float oacc[8][4];
#pragma unroll
    for (int n = 0; n < 8; ++n)
#pragma unroll
        for (int i = 0; i < 4; ++i) oacc[n][i] = 0.f;
    float m0 = -1e30f, m1 = -1e30f, l0 = 0.f, l1 = 0.f;

    const float* kb = Kg + (size_t)bh * SEQ * KDIM;
    const float* vb = Vg + (size_t)bh * SEQ * KDIM;

    // loader indices
    const int lr  = tid >> 2;             // K: row 0..63
    const int lc  = (tid & 3) << 4;       // K: col base 0/16/32/48
    const int ld2 = (tid & 31) << 1;      // V: col pair base 0..62
    const int lrr = (tid >> 5) << 3;      // V: row group base 0..56

    for (int kt = 0; kt < SEQ / 64; ++kt) {
        __syncthreads();
        {   // K tile 64x64 -> Khi/Klo [key][dpair]
            const float* kr = &kb[((size_t)(kt << 6) + lr) * KDIM + lc];
#pragma unroll
            for (int i = 0; i < 4; ++i) {
                float4 kv = *(const float4*)&kr[4 * i];
                uint32_t h0 = pack2(kv.x, kv.y), h1 = pack2(kv.z, kv.w);
                int w = lr * KW + (lc >> 1) + 2 * i;
                *(uint2*)&Khi[w] = make_uint2(h0, h1);
                *(uint2*)&Klo[w] = make_uint2(resid2(kv.x, kv.y, h0), resid2(kv.z, kv.w, h1));
            }
            // V tile 64x64 -> Vhi/Vlo [rowpair][d]
#pragma unroll
            for (int i = 0; i < 4; ++i) {
                int r0 = lrr + 2 * i;
                float2 a = *(const float2*)&vb[((size_t)(kt << 6) + r0)     * KDIM + ld2];
                float2 c = *(const float2*)&vb[((size_t)(kt << 6) + r0 + 1) * KDIM + ld2];
                uint32_t h0 = pack2(a.x, c.x), h1 = pack2(a.y, c.y);
                int w = (r0 >> 1) * VW + ld2;
                *(uint2*)&Vhi[w] = make_uint2(h0, h1);
                *(uint2*)&Vlo[w] = make_uint2(resid2(a.x, c.x, h0), resid2(a.y, c.y, h1));
            }
        }
        __syncthreads();

        // ---- S = Q K^T (16x64 per warp) ----
        float sacc[8][4];
#pragma unroll
        for (int n = 0; n < 8; ++n)
#pragma unroll
            for (int i = 0; i < 4; ++i) sacc[n][i] = 0.f;

#pragma unroll
        for (int kc = 0; kc < 4; ++kc) {
#pragma unroll
            for (int n = 0; n < 8; ++n) {
                const int wb = (n * 8 + gq) * KW + kc * 8 + tq;
                uint32_t bh0 = Khi[wb], bh1 = Khi[wb + 4];
                uint32_t bl0 = Klo[wb], bl1 = Klo[wb + 4];
                mma_bf16(sacc[n], qh[kc][0], qh[kc][1], qh[kc][2], qh[kc][3], bh0, bh1);
                mma_bf16(sacc[n], ql[kc][0], ql[kc][1], ql[kc][2], ql[kc][3], bh0, bh1);
                mma_bf16(sacc[n], qh[kc][0], qh[kc][1], qh[kc][2], qh[kc][3], bl0, bl1);
            }
        }

        // ---- online softmax (quad-reduce; row0 via c0/c1, row1 via c2/c3) ----
        float tm0 = -1e30f, tm1 = -1e30f;
#pragma unroll
        for (int n = 0; n < 8; ++n) {
            tm0 = fmaxf(tm0, fmaxf(sacc[n][0], sacc[n][1]));
            tm1 = fmaxf(tm1, fmaxf(sacc[n][2], sacc[n][3]));
        }
        tm0 = fmaxf(tm0, __shfl_xor_sync(0xffffffffu, tm0, 1));
        tm0 = fmaxf(tm0, __shfl_xor_sync(0xffffffffu, tm0, 2));
        tm1 = fmaxf(tm1, __shfl_xor_sync(0xffffffffu, tm1, 1));
        tm1 = fmaxf(tm1, __shfl_xor_sync(0xffffffffu, tm1, 2));
        float n0 = fmaxf(m0, tm0), n1 = fmaxf(m1, tm1);
        float sc0 = __expf(m0 - n0), sc1 = __expf(m1 - n1);
        m0 = n0; m1 = n1;
        float ps0 = 0.f, ps1 = 0.f;
#pragma unroll
        for (int n = 0; n < 8; ++n) {
            sacc[n][0] = __expf(sacc[n][0] - n0); ps0 += sacc[n][0];
            sacc[n][1] = __expf(sacc[n][1] - n0); ps0 += sacc[n][1];
            sacc[n][2] = __expf(sacc[n][2] - n1); ps1 += sacc[n][2];
            sacc[n][3] = __expf(sacc[n][3] - n1); ps1 += sacc[n][3];
        }
        ps0 += __shfl_xor_sync(0xffffffffu, ps0, 1);
        ps0 += __shfl_xor_sync(0xffffffffu, ps0, 2);
        ps1 += __shfl_xor_sync(0xffffffffu, ps1, 1);
        ps1 += __shfl_xor_sync(0xffffffffu, ps1, 2);
        l0 = l0 * sc0 + ps0;
        l1 = l1 * sc1 + ps1;
#pragma unroll
        for (int n = 0; n < 8; ++n) {
            oacc[n][0] *= sc0; oacc[n][1] *= sc0;
            oacc[n][2] *= sc1; oacc[n][3] *= sc1;
        }

        // ---- O += P V : accumulator pairs pack directly into A fragments ----
#pragma unroll
        for (int j = 0; j < 4; ++j) {      // 16-key chunks of P
            uint32_t ph0 = pack2(sacc[2*j][0],   sacc[2*j][1]);
            uint32_t ph1 = pack2(sacc[2*j][2],   sacc[2*j][3]);
            uint32_t ph2 = pack2(sacc[2*j+1][0], sacc[2*j+1][1]);
            uint32_t ph3 = pack2(sacc[2*j+1][2], sacc[2*j+1][3]);
            uint32_t pl0 = resid2(sacc[2*j][0],   sacc[2*j][1],   ph0);
            uint32_t pl1 = resid2(sacc[2*j][2],   sacc[2*j][3],   ph1);
            uint32_t pl2 = resid2(sacc[2*j+1][0], sacc[2*j+1][1], ph2);
            uint32_t pl3 = resid2(sacc[2*j+1][2], sacc[2*j+1][3], ph3);
#pragma unroll
            for (int dt = 0; dt < 8; ++dt) {
                const int wb = (j * 8 + tq) * VW + dt * 8 + gq;
                uint32_t bh0 = Vhi[wb], bh1 = Vhi[wb + 4 * VW];
                uint32_t bl0 = Vlo[wb], bl1 = Vlo[wb + 4 * VW];
                mma_bf16(oacc[dt], ph0, ph1, ph2, ph3, bh0, bh1);
                mma_bf16(oacc[dt], pl0, pl1, pl2, pl3, bh0, bh1);
                mma_bf16(oacc[dt], ph0, ph1, ph2, ph3, bl0, bl1);
            }
        }
    }

    // ---- normalize + write ctx [tok, h*64+d] ----
    float inv0 = 1.f / l0, inv1 = 1.f / l1;
    float* cp = Ctx + (size_t)(b * SEQ) * EMB + h * KDIM;
#pragma unroll
    for (int dt = 0; dt < 8; ++dt) {
        *(float2*)&cp[(size_t)row0 * EMB + dt * 8 + 2 * tq] =
            make_float2(oacc[dt][0] * inv0, oacc[dt][1] * inv0);
        *(float2*)&cp[(size_t)row1 * EMB + dt * 8 + 2 * tq] =
            make_float2(oacc[dt][2] * inv1, oacc[dt][3] * inv1);
    }
}

// ---------------------------------------------------------------------------
extern "C" void kernel_launch(void* const* d_in, const int* in_sizes, int n_in,
                              void* d_out, int out_size)
{
    const float* x   = (const float*)d_in[0];   // [4,2048,512]
    const float* key = (const float*)d_in[1];   // [4,8,2048,64]
    const float* val = (const float*)d_in[2];   // [4,8,2048,64]
    const float* wq  = (const float*)d_in[3];   // [512,512]
    const float* wo  = (const float*)d_in[4];   // [512,512]
    float* out = (float*)d_out;                 // [4,2048,512]

    float *qptr, *cptr;
    cudaGetSymbolAddress((void**)&qptr, g_q);
    cudaGetSymbolAddress((void**)&cptr, g_ctx);

    // 1) Q = x @ Wq   : [8192,512] x [512,512]
    gemm_bf16s<<<dim3(EMB / 64, TOKENS / 128), 256>>>(x, wq, qptr, TOKENS, EMB, EMB);
    // 2) attention    : grid (q-tiles of 128, b*h)
    attn_mma<<<dim3(SEQ / 128, BATCH * HEADS), 256>>>(qptr, key, val, cptr);
    // 3) out = ctx @ Wo
    gemm_bf16s<<<dim3(EMB / 64, TOKENS / 128), 256>>>(cptr, wo, out, TOKENS, EMB, EMB);
}